// round 11
// baseline (speedup 1.0000x reference)
#include <cuda_runtime.h>
#include <cuda_fp16.h>
#include <cstdint>
#include <cstddef>

// SubnetGate hard-routed MoE MLP, sm_103 harness (no tcgen05 under compute_103).
//   out[t] = relu(x[t] @ W1[e] + b1[e]) @ W2[e] + b2[e],  e = groups[t]
// B=8192, D_IN=512, D_H=2048, D_OUT=512, E=8, fp32 I/O (groups int32, probed).
//
// R11: GEMMs at the fp16 mma.sync issue ceiling (~97%); this round trims
// overhead: warp-aggregated router (legal full-warp ballot/shfl) and 64x64
// ILP-4 W-transpose tiles.

namespace {
constexpr int B_TOK  = 8192;
constexpr int D_IN   = 512;
constexpr int D_H    = 2048;
constexpr int D_OUT  = 512;
constexpr int NE     = 8;
constexpr int TM     = 128;
constexpr int NT_MAX = 72;            // sum ceil(c_e/128) <= 64+7
constexpr int ROWS   = NT_MAX * TM;   // 9216
constexpr int BK     = 64;            // halves per k-tile (128B rows)
constexpr int BN     = 128;
constexpr int ST     = 72;            // smem row stride in halves (conflict-free frag loads)
constexpr int AS_SZ  = TM * ST;       // halves per stage
constexpr int BS_SZ  = BN * ST;
constexpr int SMEM_BYTES = 2 * (AS_SZ + BS_SZ) * 2;   // 73728 B
}

__device__ int g_perm[ROWS];            // sorted pos -> token (-1 = pad)
__device__ int g_tile_expert[NT_MAX];   // tile -> expert (-1 inactive)
__device__ __align__(16) __half g_a1[(size_t)ROWS * D_IN];        // gathered x (half, sorted)
__device__ __align__(16) __half g_w1t[(size_t)NE * D_H * D_IN];   // W1^T [e][n][k] half
__device__ __align__(16) __half g_w2t[(size_t)NE * D_OUT * D_H];  // W2^T [e][n][k] half
__device__ __align__(16) __half g_h[(size_t)ROWS * D_H];          // hidden (half, sorted)

__device__ __forceinline__ uint32_t h2_as_u32(__half2 h) {
    return *reinterpret_cast<uint32_t*>(&h);
}

__device__ __forceinline__ void cp_async16(void* smem_dst, const void* gsrc) {
    uint32_t s = (uint32_t)__cvta_generic_to_shared(smem_dst);
    asm volatile("cp.async.cg.shared.global [%0], [%1], 16;\n" :: "r"(s), "l"(gsrc));
}

// ---------------------------------------------------------------------------
// Router: single block, warp-aggregated counting sort into 128-row padded
// per-expert tiles. All ballot/shfl executed by full warps (uniform loops);
// only the final store is predicated. Probes int32 vs int64 groups layout.
// ---------------------------------------------------------------------------
__global__ void route_kernel(const int* __restrict__ g32) {
    __shared__ int cnt[NE];
    __shared__ int base[NE + 1];
    __shared__ int cur[NE];
    __shared__ int odd_or;
    const int tid  = threadIdx.x;
    const int lane = tid & 31;

    if (tid < NE) cnt[tid] = 0;
    if (tid == 0) odd_or = 0;
    __syncthreads();

    // dtype probe: int64 data (values 0..7, LE) => all odd int32 words zero.
    // B_TOK multiple of 2*blockDim -> uniform trip count for all threads.
    int acc_or = 0;
    for (int i = 2 * tid + 1; i < B_TOK; i += 2 * blockDim.x) acc_or |= g32[i];
    if (acc_or) atomicOr(&odd_or, 1);
    __syncthreads();
    const bool is_i32 = (odd_or != 0);

    // Count pass: warp-aggregated (ballot by all lanes, one atomic per warp).
    for (int t = tid; t < B_TOK; t += blockDim.x) {   // uniform: 8 iters each
        int e = (is_i32 ? g32[t] : g32[2 * t]) & (NE - 1);
#pragma unroll
        for (int ee = 0; ee < NE; ee++) {
            unsigned m = __ballot_sync(0xffffffffu, e == ee);
            if (m && lane == (unsigned)(__ffs(m) - 1)) atomicAdd(&cnt[ee], __popc(m));
        }
    }
    __syncthreads();

    if (tid == 0) {
        int b = 0;
        for (int e = 0; e < NE; e++) {
            base[e] = b; cur[e] = b;
            b += ((cnt[e] + TM - 1) / TM) * TM;
        }
        base[NE] = b;
    }
    __syncthreads();

    for (int i = tid; i < ROWS; i += blockDim.x) g_perm[i] = -1;
    for (int t = tid; t < NT_MAX; t += blockDim.x) {
        int row0 = t * TM;
        int e = -1;
        if (row0 < base[NE])
            for (int k = 0; k < NE; k++)
                if (row0 >= base[k] && row0 < base[k + 1]) e = k;
        g_tile_expert[t] = e;
    }
    __syncthreads();

    // Scatter pass: ballot + leader atomic + FULL-WARP shfl (legal), then
    // predicated store with intra-warp rank.
    for (int t = tid; t < B_TOK; t += blockDim.x) {   // uniform: 8 iters each
        int e = (is_i32 ? g32[t] : g32[2 * t]) & (NE - 1);
#pragma unroll
        for (int ee = 0; ee < NE; ee++) {
            unsigned m = __ballot_sync(0xffffffffu, e == ee);
            if (m) {                                   // warp-uniform predicate
                int ldr = __ffs(m) - 1;
                int start = 0;
                if (lane == ldr) start = atomicAdd(&cur[ee], __popc(m));
                start = __shfl_sync(0xffffffffu, start, ldr);  // all lanes execute
                if (e == ee)
                    g_perm[start + __popc(m & ((1u << lane) - 1))] = t;
            }
        }
    }
}

// ---------------------------------------------------------------------------
// Prep: gather x rows into sorted padded layout, converted to half.
// Block b covers rows 2b, 2b+1; thread handles 4 floats -> 2 half2 (8B store).
// ---------------------------------------------------------------------------
__global__ void prep_x_kernel(const float* __restrict__ x) {
    const int tid = threadIdx.x;
    const int row = 2 * blockIdx.x + (tid >> 7);
    const int c4  = (tid & 127) * 4;
    const int tok = g_perm[row];
    float4 v = make_float4(0.f, 0.f, 0.f, 0.f);
    if (tok >= 0) v = *(const float4*)(x + (size_t)tok * D_IN + c4);
    uint2 o;
    o.x = h2_as_u32(__floats2half2_rn(v.x, v.y));
    o.y = h2_as_u32(__floats2half2_rn(v.z, v.w));
    *(uint2*)(g_a1 + (size_t)row * D_IN + c4) = o;
}

// ---------------------------------------------------------------------------
// Prep: transpose W [e][K][N] -> W^T [e][N][K], converted to half.
// 64x64 smem tiles, 4 float4 loads + 4 uint2 stores per thread (ILP 4).
// grid (N/64, K/64, E), 256 threads.
// ---------------------------------------------------------------------------
template <int K, int N, bool W2SEL>
__global__ void prep_w_kernel(const float* __restrict__ src) {
    __shared__ float s[64][65];
    __half* dst = W2SEL ? g_w2t : g_w1t;
    const int tid = threadIdx.x;
    const int bn = blockIdx.x, bk = blockIdx.y, e = blockIdx.z;
    const int r  = tid >> 4;        // 0..15
    const int cg = tid & 15;        // 0..15

#pragma unroll
    for (int q = 0; q < 4; q++) {
        int row = r + 16 * q;
        float4 v = *(const float4*)(src + ((size_t)e * K + 64 * bk + row) * N
                                        + 64 * bn + cg * 4);
        s[row][cg * 4 + 0] = v.x; s[row][cg * 4 + 1] = v.y;
        s[row][cg * 4 + 2] = v.z; s[row][cg * 4 + 3] = v.w;
    }
    __syncthreads();

#pragma unroll
    for (int q = 0; q < 4; q++) {
        int n = r + 16 * q;
        uint2 o;
        o.x = h2_as_u32(__floats2half2_rn(s[cg * 4 + 0][n], s[cg * 4 + 1][n]));
        o.y = h2_as_u32(__floats2half2_rn(s[cg * 4 + 2][n], s[cg * 4 + 3][n]));
        *(uint2*)(dst + ((size_t)e * N + 64 * bn + n) * K + 64 * bk + cg * 4) = o;
    }
}

// ---------------------------------------------------------------------------
// Grouped GEMM: C = op(A_sorted @ W^T[e] + bias[e])
// 128x128 block tile, BK=64, 8 warps (2x4), 64x32 warp tile, fp16 m16n8k16,
// fp32 accumulate, cp.async double-buffer.
//   LAYER1: A=g_a1, W=g_w1t, relu, -> g_h (half, sorted)
//  !LAYER1: A=g_h,  W=g_w2t,       -> scatter fp32 to out
// ---------------------------------------------------------------------------
template <int K, int NTOT, bool LAYER1>
__global__ __launch_bounds__(256, 2)
void gemm_kernel(const float* __restrict__ bias, float* __restrict__ Oout) {
    extern __shared__ __half smem[];
    __half* AsBase = smem;                    // 2 stages TM x BK (stride ST)
    __half* BsBase = smem + 2 * AS_SZ;        // 2 stages BN x BK (stride ST)

    const int tile = blockIdx.x;
    const int e = g_tile_expert[tile];
    if (e < 0) return;

    const __half* Abase = LAYER1 ? g_a1 : g_h;      // device-side symbol refs
    const __half* Wt    = LAYER1 ? g_w1t : g_w2t;

    const int n0 = blockIdx.y * BN;
    const __half* Arow0 = Abase + (size_t)tile * TM * K;
    const __half* Brow0 = Wt + ((size_t)e * NTOT + n0) * K;
    const float*  bp    = bias + (size_t)e * NTOT + n0;

    const int tid  = threadIdx.x;
    const int lane = tid & 31;
    const int warp = tid >> 5;
    const int wm   = warp >> 2;  // 0..1
    const int wn   = warp & 3;   // 0..3

    float acc[4][4][4];
#pragma unroll
    for (int i = 0; i < 4; i++)
#pragma unroll
        for (int j = 0; j < 4; j++)
#pragma unroll
            for (int q = 0; q < 4; q++) acc[i][j][q] = 0.f;

    // Stage 128 rows x 64 halves for A and B: 1024 16B-chunks each, 256 thr x 4.
    auto stage = [&](int k0, int buf) {
        __half* as = AsBase + buf * AS_SZ;
        __half* bs = BsBase + buf * BS_SZ;
#pragma unroll
        for (int j = 0; j < 4; j++) {
            int c = tid + 256 * j;
            int r = c >> 3;
            int co = (c & 7) * 8;
            cp_async16(&as[r * ST + co], Arow0 + (size_t)r * K + k0 + co);
        }
#pragma unroll
        for (int j = 0; j < 4; j++) {
            int c = tid + 256 * j;
            int r = c >> 3;
            int co = (c & 7) * 8;
            cp_async16(&bs[r * ST + co], Brow0 + (size_t)r * K + k0 + co);
        }
    };

    constexpr int NIT = K / BK;

    stage(0, 0);
    asm volatile("cp.async.commit_group;\n");

    for (int it = 0; it < NIT; it++) {
        const int buf = it & 1;
        if (it + 1 < NIT) {
            stage((it + 1) * BK, buf ^ 1);
            asm volatile("cp.async.commit_group;\n");
            asm volatile("cp.async.wait_group 1;\n");
        } else {
            asm volatile("cp.async.wait_group 0;\n");
        }
        __syncthreads();

        const __half* As = AsBase + buf * AS_SZ;
        const __half* Bs = BsBase + buf * BS_SZ;

#pragma unroll
        for (int ks = 0; ks < BK / 16; ks++) {
            const int kq = ks * 16 + (lane & 3) * 2;
            uint32_t af[4][4], bf[4][2];
#pragma unroll
            for (int mf = 0; mf < 4; mf++) {
                int m = wm * 64 + mf * 16 + (lane >> 2);
                // m16n8k16 f16 A frag: a0=(m,k:k+1) a1=(m+8,k:k+1) a2=(m,k+8:k+9) a3=(m+8,k+8:k+9)
                af[mf][0] = *(const uint32_t*)&As[m * ST + kq];
                af[mf][1] = *(const uint32_t*)&As[(m + 8) * ST + kq];
                af[mf][2] = *(const uint32_t*)&As[m * ST + kq + 8];
                af[mf][3] = *(const uint32_t*)&As[(m + 8) * ST + kq + 8];
            }
#pragma unroll
            for (int nf = 0; nf < 4; nf++) {
                int n = wn * 32 + nf * 8 + (lane >> 2);
                // B frag (col): b0=(k:k+1, n), b1=(k+8:k+9, n); Bs rows n-major, k contiguous
                bf[nf][0] = *(const uint32_t*)&Bs[n * ST + kq];
                bf[nf][1] = *(const uint32_t*)&Bs[n * ST + kq + 8];
            }
#pragma unroll
            for (int mf = 0; mf < 4; mf++)
#pragma unroll
                for (int nf = 0; nf < 4; nf++) {
                    asm volatile(
                        "mma.sync.aligned.m16n8k16.row.col.f32.f16.f16.f32 "
                        "{%0,%1,%2,%3}, {%4,%5,%6,%7}, {%8,%9}, {%0,%1,%2,%3};\n"
                        : "+f"(acc[mf][nf][0]), "+f"(acc[mf][nf][1]),
                          "+f"(acc[mf][nf][2]), "+f"(acc[mf][nf][3])
                        : "r"(af[mf][0]), "r"(af[mf][1]),
                          "r"(af[mf][2]), "r"(af[mf][3]),
                          "r"(bf[nf][0]), "r"(bf[nf][1]));
                }
        }
        __syncthreads();
    }

    // Epilogue: bias (+relu); layer1 -> half g_h (sorted), layer2 -> scatter fp32.
#pragma unroll
    for (int mf = 0; mf < 4; mf++) {
#pragma unroll
        for (int half_i = 0; half_i < 2; half_i++) {
            int r = wm * 64 + mf * 16 + (lane >> 2) + half_i * 8;
            float* orow_f = nullptr;
            __half* orow_h = nullptr;
            if (!LAYER1) {
                int tok = g_perm[tile * TM + r];
                if (tok >= 0) orow_f = Oout + (size_t)tok * NTOT + n0;
            } else {
                orow_h = g_h + ((size_t)tile * TM + r) * NTOT + n0;
            }
#pragma unroll
            for (int nf = 0; nf < 4; nf++) {
                int c = wn * 32 + nf * 8 + 2 * (lane & 3);
                float v0 = acc[mf][nf][half_i * 2 + 0] + bp[c];
                float v1 = acc[mf][nf][half_i * 2 + 1] + bp[c + 1];
                if (LAYER1) { v0 = fmaxf(v0, 0.f); v1 = fmaxf(v1, 0.f); }
                if (!LAYER1) {
                    if (orow_f) { orow_f[c] = v0; orow_f[c + 1] = v1; }
                } else {
                    *(uint32_t*)&orow_h[c] = h2_as_u32(__floats2half2_rn(v0, v1));
                }
            }
        }
    }
}

extern "C" void kernel_launch(void* const* d_in, const int* in_sizes, int n_in,
                              void* d_out, int out_size) {
    const float* x      = (const float*)d_in[0];
    const int*   groups = (const int*)d_in[1];
    const float* W1     = (const float*)d_in[2];
    const float* b1     = (const float*)d_in[3];
    const float* W2     = (const float*)d_in[4];
    const float* b2     = (const float*)d_in[5];
    float*       out    = (float*)d_out;

    cudaFuncSetAttribute(gemm_kernel<D_IN, D_H, true>,
                         cudaFuncAttributeMaxDynamicSharedMemorySize, SMEM_BYTES);
    cudaFuncSetAttribute(gemm_kernel<D_H, D_OUT, false>,
                         cudaFuncAttributeMaxDynamicSharedMemorySize, SMEM_BYTES);

    route_kernel<<<1, 1024>>>(groups);
    prep_x_kernel<<<ROWS / 2, 256>>>(x);
    prep_w_kernel<D_IN, D_H, false><<<dim3(D_H / 64, D_IN / 64, NE), 256>>>(W1);
    prep_w_kernel<D_H, D_OUT, true><<<dim3(D_OUT / 64, D_H / 64, NE), 256>>>(W2);

    // Layer 1: h = relu(x_sorted @ W1^T[e] + b1[e]) -> g_h (half, sorted)
    gemm_kernel<D_IN, D_H, true>
        <<<dim3(NT_MAX, D_H / BN), 256, SMEM_BYTES>>>(b1, nullptr);

    // Layer 2: out[tok] = h @ W2^T[e] + b2[e] (scatter to token order, fp32)
    gemm_kernel<D_H, D_OUT, false>
        <<<dim3(NT_MAX, D_OUT / BN), 256, SMEM_BYTES>>>(b2, out);
}

// round 12
// speedup vs baseline: 1.1152x; 1.1152x over previous
#include <cuda_runtime.h>
#include <cuda_fp16.h>
#include <cstdint>
#include <cstddef>

// SubnetGate hard-routed MoE MLP, sm_103 harness (no tcgen05 under compute_103).
//   out[t] = relu(x[t] @ W1[e] + b1[e]) @ W2[e] + b2[e],  e = groups[t]
// B=8192, D_IN=512, D_H=2048, D_OUT=512, E=8, fp32 I/O (groups int32, probed).
//
// R12: R10-exact kernels (known-good 176.6us) + capture-legal fork/join stream
// overlap: prep_w (W transpose, no deps on routing) runs on a side stream
// concurrently with route+prep_x, hiding ~20us of the ~37us non-GEMM overhead.

namespace {
constexpr int B_TOK  = 8192;
constexpr int D_IN   = 512;
constexpr int D_H    = 2048;
constexpr int D_OUT  = 512;
constexpr int NE     = 8;
constexpr int TM     = 128;
constexpr int NT_MAX = 72;            // sum ceil(c_e/128) <= 64+7
constexpr int ROWS   = NT_MAX * TM;   // 9216
constexpr int BK     = 64;            // halves per k-tile (128B rows)
constexpr int BN     = 128;
constexpr int ST     = 72;            // smem row stride in halves (conflict-free frag loads)
constexpr int AS_SZ  = TM * ST;       // halves per stage
constexpr int BS_SZ  = BN * ST;
constexpr int SMEM_BYTES = 2 * (AS_SZ + BS_SZ) * 2;   // 73728 B
}

__device__ int g_perm[ROWS];            // sorted pos -> token (-1 = pad)
__device__ int g_tile_expert[NT_MAX];   // tile -> expert (-1 inactive)
__device__ __align__(16) __half g_a1[(size_t)ROWS * D_IN];        // gathered x (half, sorted)
__device__ __align__(16) __half g_w1t[(size_t)NE * D_H * D_IN];   // W1^T [e][n][k] half
__device__ __align__(16) __half g_w2t[(size_t)NE * D_OUT * D_H];  // W2^T [e][n][k] half
__device__ __align__(16) __half g_h[(size_t)ROWS * D_H];          // hidden (half, sorted)

__device__ __forceinline__ uint32_t h2_as_u32(__half2 h) {
    return *reinterpret_cast<uint32_t*>(&h);
}

__device__ __forceinline__ void cp_async16(void* smem_dst, const void* gsrc) {
    uint32_t s = (uint32_t)__cvta_generic_to_shared(smem_dst);
    asm volatile("cp.async.cg.shared.global [%0], [%1], 16;\n" :: "r"(s), "l"(gsrc));
}

// ---------------------------------------------------------------------------
// Router (R10-proven): single block, shared-counter counting sort into
// 128-row padded per-expert tiles. Probes int32 vs int64 groups layout.
// ---------------------------------------------------------------------------
__global__ void route_kernel(const int* __restrict__ g32) {
    __shared__ int cnt[NE];
    __shared__ int base[NE + 1];
    __shared__ int cur[NE];
    __shared__ int odd_or;
    const int tid = threadIdx.x;

    if (tid < NE) cnt[tid] = 0;
    if (tid == 0) odd_or = 0;
    __syncthreads();

    // dtype probe: int64 data (values 0..7, LE) => all odd int32 words zero
    int acc_or = 0;
    for (int i = 2 * tid + 1; i < B_TOK; i += 2 * blockDim.x) acc_or |= g32[i];
    if (acc_or) atomicOr(&odd_or, 1);
    __syncthreads();
    const bool is_i32 = (odd_or != 0);

    for (int t = tid; t < B_TOK; t += blockDim.x) {
        int e = (is_i32 ? g32[t] : g32[2 * t]) & (NE - 1);
        atomicAdd(&cnt[e], 1);
    }
    __syncthreads();

    if (tid == 0) {
        int b = 0;
        for (int e = 0; e < NE; e++) {
            base[e] = b; cur[e] = b;
            b += ((cnt[e] + TM - 1) / TM) * TM;
        }
        base[NE] = b;
    }
    __syncthreads();

    for (int i = tid; i < ROWS; i += blockDim.x) g_perm[i] = -1;
    for (int t = tid; t < NT_MAX; t += blockDim.x) {
        int row0 = t * TM;
        int e = -1;
        if (row0 < base[NE])
            for (int k = 0; k < NE; k++)
                if (row0 >= base[k] && row0 < base[k + 1]) e = k;
        g_tile_expert[t] = e;
    }
    __syncthreads();

    for (int t = tid; t < B_TOK; t += blockDim.x) {
        int e = (is_i32 ? g32[t] : g32[2 * t]) & (NE - 1);
        int pos = atomicAdd(&cur[e], 1);
        g_perm[pos] = t;
    }
}

// ---------------------------------------------------------------------------
// Prep: gather x rows into sorted padded layout, converted to half.
// Block b covers rows 2b, 2b+1; thread handles 4 floats -> 2 half2 (8B store).
// ---------------------------------------------------------------------------
__global__ void prep_x_kernel(const float* __restrict__ x) {
    const int tid = threadIdx.x;
    const int row = 2 * blockIdx.x + (tid >> 7);
    const int c4  = (tid & 127) * 4;
    const int tok = g_perm[row];
    float4 v = make_float4(0.f, 0.f, 0.f, 0.f);
    if (tok >= 0) v = *(const float4*)(x + (size_t)tok * D_IN + c4);
    uint2 o;
    o.x = h2_as_u32(__floats2half2_rn(v.x, v.y));
    o.y = h2_as_u32(__floats2half2_rn(v.z, v.w));
    *(uint2*)(g_a1 + (size_t)row * D_IN + c4) = o;
}

// ---------------------------------------------------------------------------
// Prep (R10-proven): transpose W [e][K][N] -> W^T [e][N][K], converted to half.
// 32x32 fp32 smem tiles; grid (N/32, K/32, E), 256 threads.
// ---------------------------------------------------------------------------
template <int K, int N, bool W2SEL>
__global__ void prep_w_kernel(const float* __restrict__ src) {
    __shared__ float s[32][33];
    __half* dst = W2SEL ? g_w2t : g_w1t;
    const int tid = threadIdx.x;
    const int bn = blockIdx.x, bk = blockIdx.y, e = blockIdx.z;
    const int r  = tid >> 3;
    const int c4 = (tid & 7) * 4;

    float4 v = *(const float4*)(src + ((size_t)e * K + 32 * bk + r) * N + 32 * bn + c4);
    s[r][c4 + 0] = v.x; s[r][c4 + 1] = v.y; s[r][c4 + 2] = v.z; s[r][c4 + 3] = v.w;
    __syncthreads();

    uint2 o;
    o.x = h2_as_u32(__floats2half2_rn(s[c4 + 0][r], s[c4 + 1][r]));
    o.y = h2_as_u32(__floats2half2_rn(s[c4 + 2][r], s[c4 + 3][r]));
    *(uint2*)(dst + ((size_t)e * N + 32 * bn + r) * K + 32 * bk + c4) = o;
}

// ---------------------------------------------------------------------------
// Grouped GEMM: C = op(A_sorted @ W^T[e] + bias[e])
// 128x128 block tile, BK=64, 8 warps (2x4), 64x32 warp tile, fp16 m16n8k16,
// fp32 accumulate, cp.async double-buffer.
//   LAYER1: A=g_a1, W=g_w1t, relu, -> g_h (half, sorted)
//  !LAYER1: A=g_h,  W=g_w2t,       -> scatter fp32 to out
// ---------------------------------------------------------------------------
template <int K, int NTOT, bool LAYER1>
__global__ __launch_bounds__(256, 2)
void gemm_kernel(const float* __restrict__ bias, float* __restrict__ Oout) {
    extern __shared__ __half smem[];
    __half* AsBase = smem;                    // 2 stages TM x BK (stride ST)
    __half* BsBase = smem + 2 * AS_SZ;        // 2 stages BN x BK (stride ST)

    const int tile = blockIdx.x;
    const int e = g_tile_expert[tile];
    if (e < 0) return;

    const __half* Abase = LAYER1 ? g_a1 : g_h;      // device-side symbol refs
    const __half* Wt    = LAYER1 ? g_w1t : g_w2t;

    const int n0 = blockIdx.y * BN;
    const __half* Arow0 = Abase + (size_t)tile * TM * K;
    const __half* Brow0 = Wt + ((size_t)e * NTOT + n0) * K;
    const float*  bp    = bias + (size_t)e * NTOT + n0;

    const int tid  = threadIdx.x;
    const int lane = tid & 31;
    const int warp = tid >> 5;
    const int wm   = warp >> 2;  // 0..1
    const int wn   = warp & 3;   // 0..3

    float acc[4][4][4];
#pragma unroll
    for (int i = 0; i < 4; i++)
#pragma unroll
        for (int j = 0; j < 4; j++)
#pragma unroll
            for (int q = 0; q < 4; q++) acc[i][j][q] = 0.f;

    // Stage 128 rows x 64 halves for A and B: 1024 16B-chunks each, 256 thr x 4.
    auto stage = [&](int k0, int buf) {
        __half* as = AsBase + buf * AS_SZ;
        __half* bs = BsBase + buf * BS_SZ;
#pragma unroll
        for (int j = 0; j < 4; j++) {
            int c = tid + 256 * j;
            int r = c >> 3;
            int co = (c & 7) * 8;
            cp_async16(&as[r * ST + co], Arow0 + (size_t)r * K + k0 + co);
        }
#pragma unroll
        for (int j = 0; j < 4; j++) {
            int c = tid + 256 * j;
            int r = c >> 3;
            int co = (c & 7) * 8;
            cp_async16(&bs[r * ST + co], Brow0 + (size_t)r * K + k0 + co);
        }
    };

    constexpr int NIT = K / BK;

    stage(0, 0);
    asm volatile("cp.async.commit_group;\n");

    for (int it = 0; it < NIT; it++) {
        const int buf = it & 1;
        if (it + 1 < NIT) {
            stage((it + 1) * BK, buf ^ 1);
            asm volatile("cp.async.commit_group;\n");
            asm volatile("cp.async.wait_group 1;\n");
        } else {
            asm volatile("cp.async.wait_group 0;\n");
        }
        __syncthreads();

        const __half* As = AsBase + buf * AS_SZ;
        const __half* Bs = BsBase + buf * BS_SZ;

#pragma unroll
        for (int ks = 0; ks < BK / 16; ks++) {
            const int kq = ks * 16 + (lane & 3) * 2;
            uint32_t af[4][4], bf[4][2];
#pragma unroll
            for (int mf = 0; mf < 4; mf++) {
                int m = wm * 64 + mf * 16 + (lane >> 2);
                // m16n8k16 f16 A frag: a0=(m,k:k+1) a1=(m+8,k:k+1) a2=(m,k+8:k+9) a3=(m+8,k+8:k+9)
                af[mf][0] = *(const uint32_t*)&As[m * ST + kq];
                af[mf][1] = *(const uint32_t*)&As[(m + 8) * ST + kq];
                af[mf][2] = *(const uint32_t*)&As[m * ST + kq + 8];
                af[mf][3] = *(const uint32_t*)&As[(m + 8) * ST + kq + 8];
            }
#pragma unroll
            for (int nf = 0; nf < 4; nf++) {
                int n = wn * 32 + nf * 8 + (lane >> 2);
                // B frag (col): b0=(k:k+1, n), b1=(k+8:k+9, n); Bs rows n-major, k contiguous
                bf[nf][0] = *(const uint32_t*)&Bs[n * ST + kq];
                bf[nf][1] = *(const uint32_t*)&Bs[n * ST + kq + 8];
            }
#pragma unroll
            for (int mf = 0; mf < 4; mf++)
#pragma unroll
                for (int nf = 0; nf < 4; nf++) {
                    asm volatile(
                        "mma.sync.aligned.m16n8k16.row.col.f32.f16.f16.f32 "
                        "{%0,%1,%2,%3}, {%4,%5,%6,%7}, {%8,%9}, {%0,%1,%2,%3};\n"
                        : "+f"(acc[mf][nf][0]), "+f"(acc[mf][nf][1]),
                          "+f"(acc[mf][nf][2]), "+f"(acc[mf][nf][3])
                        : "r"(af[mf][0]), "r"(af[mf][1]),
                          "r"(af[mf][2]), "r"(af[mf][3]),
                          "r"(bf[nf][0]), "r"(bf[nf][1]));
                }
        }
        __syncthreads();
    }

    // Epilogue: bias (+relu); layer1 -> half g_h (sorted), layer2 -> scatter fp32.
#pragma unroll
    for (int mf = 0; mf < 4; mf++) {
#pragma unroll
        for (int half_i = 0; half_i < 2; half_i++) {
            int r = wm * 64 + mf * 16 + (lane >> 2) + half_i * 8;
            float* orow_f = nullptr;
            __half* orow_h = nullptr;
            if (!LAYER1) {
                int tok = g_perm[tile * TM + r];
                if (tok >= 0) orow_f = Oout + (size_t)tok * NTOT + n0;
            } else {
                orow_h = g_h + ((size_t)tile * TM + r) * NTOT + n0;
            }
#pragma unroll
            for (int nf = 0; nf < 4; nf++) {
                int c = wn * 32 + nf * 8 + 2 * (lane & 3);
                float v0 = acc[mf][nf][half_i * 2 + 0] + bp[c];
                float v1 = acc[mf][nf][half_i * 2 + 1] + bp[c + 1];
                if (LAYER1) { v0 = fmaxf(v0, 0.f); v1 = fmaxf(v1, 0.f); }
                if (!LAYER1) {
                    if (orow_f) { orow_f[c] = v0; orow_f[c + 1] = v1; }
                } else {
                    *(uint32_t*)&orow_h[c] = h2_as_u32(__floats2half2_rn(v0, v1));
                }
            }
        }
    }
}

extern "C" void kernel_launch(void* const* d_in, const int* in_sizes, int n_in,
                              void* d_out, int out_size) {
    const float* x      = (const float*)d_in[0];
    const int*   groups = (const int*)d_in[1];
    const float* W1     = (const float*)d_in[2];
    const float* b1     = (const float*)d_in[3];
    const float* W2     = (const float*)d_in[4];
    const float* b2     = (const float*)d_in[5];
    float*       out    = (float*)d_out;

    // One-time side stream + events for capture-legal fork/join. Created once;
    // work per call is identical (deterministic graph).
    static cudaStream_t s2 = nullptr;
    static cudaEvent_t evFork = nullptr, evW1 = nullptr, evW2 = nullptr;
    if (!s2) {
        cudaStreamCreateWithFlags(&s2, cudaStreamNonBlocking);
        cudaEventCreateWithFlags(&evFork, cudaEventDisableTiming);
        cudaEventCreateWithFlags(&evW1,   cudaEventDisableTiming);
        cudaEventCreateWithFlags(&evW2,   cudaEventDisableTiming);
    }

    cudaFuncSetAttribute(gemm_kernel<D_IN, D_H, true>,
                         cudaFuncAttributeMaxDynamicSharedMemorySize, SMEM_BYTES);
    cudaFuncSetAttribute(gemm_kernel<D_H, D_OUT, false>,
                         cudaFuncAttributeMaxDynamicSharedMemorySize, SMEM_BYTES);

    // Fork: prep_w (independent of routing) on side stream.
    cudaEventRecord(evFork, 0);
    cudaStreamWaitEvent(s2, evFork, 0);
    prep_w_kernel<D_IN, D_H, false><<<dim3(D_H / 32, D_IN / 32, NE), 256, 0, s2>>>(W1);
    cudaEventRecord(evW1, s2);
    prep_w_kernel<D_H, D_OUT, true><<<dim3(D_OUT / 32, D_H / 32, NE), 256, 0, s2>>>(W2);
    cudaEventRecord(evW2, s2);

    // Main stream: route -> prep_x (runs concurrently with prep_w).
    route_kernel<<<1, 1024>>>(groups);
    prep_x_kernel<<<ROWS / 2, 256>>>(x);

    // Join W1^T before GEMM1; W2^T before GEMM2 (long since done by then).
    cudaStreamWaitEvent(0, evW1, 0);
    gemm_kernel<D_IN, D_H, true>
        <<<dim3(NT_MAX, D_H / BN), 256, SMEM_BYTES>>>(b1, nullptr);

    cudaStreamWaitEvent(0, evW2, 0);
    gemm_kernel<D_H, D_OUT, false>
        <<<dim3(NT_MAX, D_OUT / BN), 256, SMEM_BYTES>>>(b2, out);
}

// round 13
// speedup vs baseline: 1.1244x; 1.0082x over previous
#include <cuda_runtime.h>
#include <cuda_fp16.h>
#include <cstdint>
#include <cstddef>

// SubnetGate hard-routed MoE MLP, sm_103 harness (no tcgen05 under compute_103).
//   out[t] = relu(x[t] @ W1[e] + b1[e]) @ W2[e] + b2[e],  e = groups[t]
// B=8192, D_IN=512, D_H=2048, D_OUT=512, E=8, fp32 I/O (groups int32, probed).
//
// R13: take prep_x off the critical path. x is converted to half in TOKEN
// order (no routing dependency -> runs at t=0 on its own stream); GEMM1
// gathers A rows via g_perm during cp.async staging (zero-fill for pads).
// Critical path: max(route, W1^T, convert_x) + GEMM1 + GEMM2.

namespace {
constexpr int B_TOK  = 8192;
constexpr int D_IN   = 512;
constexpr int D_H    = 2048;
constexpr int D_OUT  = 512;
constexpr int NE     = 8;
constexpr int TM     = 128;
constexpr int NT_MAX = 72;            // sum ceil(c_e/128) <= 64+7
constexpr int ROWS   = NT_MAX * TM;   // 9216
constexpr int BK     = 64;            // halves per k-tile (128B rows)
constexpr int BN     = 128;
constexpr int ST     = 72;            // smem row stride in halves (conflict-free frag loads)
constexpr int AS_SZ  = TM * ST;       // halves per stage
constexpr int BS_SZ  = BN * ST;
constexpr int SMEM_BYTES = 2 * (AS_SZ + BS_SZ) * 2;   // 73728 B
}

__device__ int g_perm[ROWS];            // sorted pos -> token (-1 = pad)
__device__ int g_tile_expert[NT_MAX];   // tile -> expert (-1 inactive)
__device__ __align__(16) __half g_a1[(size_t)B_TOK * D_IN];       // x as half, TOKEN order
__device__ __align__(16) __half g_w1t[(size_t)NE * D_H * D_IN];   // W1^T [e][n][k] half
__device__ __align__(16) __half g_w2t[(size_t)NE * D_OUT * D_H];  // W2^T [e][n][k] half
__device__ __align__(16) __half g_h[(size_t)ROWS * D_H];          // hidden (half, sorted)

__device__ __forceinline__ uint32_t h2_as_u32(__half2 h) {
    return *reinterpret_cast<uint32_t*>(&h);
}

__device__ __forceinline__ void cp_async16(void* smem_dst, const void* gsrc) {
    uint32_t s = (uint32_t)__cvta_generic_to_shared(smem_dst);
    asm volatile("cp.async.cg.shared.global [%0], [%1], 16;\n" :: "r"(s), "l"(gsrc));
}
// Predicated variant: pred=false => src-size 0 => zero-fill 16B.
__device__ __forceinline__ void cp_async16_z(void* smem_dst, const void* gsrc, bool pred) {
    uint32_t s = (uint32_t)__cvta_generic_to_shared(smem_dst);
    int sz = pred ? 16 : 0;
    asm volatile("cp.async.cg.shared.global [%0], [%1], 16, %2;\n"
                 :: "r"(s), "l"(gsrc), "r"(sz));
}

// ---------------------------------------------------------------------------
// Router (R10-proven): single block, shared-counter counting sort into
// 128-row padded per-expert tiles. Probes int32 vs int64 groups layout.
// ---------------------------------------------------------------------------
__global__ void route_kernel(const int* __restrict__ g32) {
    __shared__ int cnt[NE];
    __shared__ int base[NE + 1];
    __shared__ int cur[NE];
    __shared__ int odd_or;
    const int tid = threadIdx.x;

    if (tid < NE) cnt[tid] = 0;
    if (tid == 0) odd_or = 0;
    __syncthreads();

    // dtype probe: int64 data (values 0..7, LE) => all odd int32 words zero
    int acc_or = 0;
    for (int i = 2 * tid + 1; i < B_TOK; i += 2 * blockDim.x) acc_or |= g32[i];
    if (acc_or) atomicOr(&odd_or, 1);
    __syncthreads();
    const bool is_i32 = (odd_or != 0);

    for (int t = tid; t < B_TOK; t += blockDim.x) {
        int e = (is_i32 ? g32[t] : g32[2 * t]) & (NE - 1);
        atomicAdd(&cnt[e], 1);
    }
    __syncthreads();

    if (tid == 0) {
        int b = 0;
        for (int e = 0; e < NE; e++) {
            base[e] = b; cur[e] = b;
            b += ((cnt[e] + TM - 1) / TM) * TM;
        }
        base[NE] = b;
    }
    __syncthreads();

    for (int i = tid; i < ROWS; i += blockDim.x) g_perm[i] = -1;
    for (int t = tid; t < NT_MAX; t += blockDim.x) {
        int row0 = t * TM;
        int e = -1;
        if (row0 < base[NE])
            for (int k = 0; k < NE; k++)
                if (row0 >= base[k] && row0 < base[k + 1]) e = k;
        g_tile_expert[t] = e;
    }
    __syncthreads();

    for (int t = tid; t < B_TOK; t += blockDim.x) {
        int e = (is_i32 ? g32[t] : g32[2 * t]) & (NE - 1);
        int pos = atomicAdd(&cur[e], 1);
        g_perm[pos] = t;
    }
}

// ---------------------------------------------------------------------------
// Convert x -> half in TOKEN order (no routing dependency; coalesced).
// Each thread: 8 floats -> 16B half store. grid 2048 x 256.
// ---------------------------------------------------------------------------
__global__ void convert_x_kernel(const float* __restrict__ x) {
    const size_t base = ((size_t)blockIdx.x * 256 + threadIdx.x) * 8;
    float4 a = *(const float4*)(x + base);
    float4 b = *(const float4*)(x + base + 4);
    uint4 o;
    o.x = h2_as_u32(__floats2half2_rn(a.x, a.y));
    o.y = h2_as_u32(__floats2half2_rn(a.z, a.w));
    o.z = h2_as_u32(__floats2half2_rn(b.x, b.y));
    o.w = h2_as_u32(__floats2half2_rn(b.z, b.w));
    *(uint4*)(g_a1 + base) = o;
}

// ---------------------------------------------------------------------------
// Prep (R10-proven): transpose W [e][K][N] -> W^T [e][N][K], converted to half.
// 32x32 fp32 smem tiles; grid (N/32, K/32, E), 256 threads.
// ---------------------------------------------------------------------------
template <int K, int N, bool W2SEL>
__global__ void prep_w_kernel(const float* __restrict__ src) {
    __shared__ float s[32][33];
    __half* dst = W2SEL ? g_w2t : g_w1t;
    const int tid = threadIdx.x;
    const int bn = blockIdx.x, bk = blockIdx.y, e = blockIdx.z;
    const int r  = tid >> 3;
    const int c4 = (tid & 7) * 4;

    float4 v = *(const float4*)(src + ((size_t)e * K + 32 * bk + r) * N + 32 * bn + c4);
    s[r][c4 + 0] = v.x; s[r][c4 + 1] = v.y; s[r][c4 + 2] = v.z; s[r][c4 + 3] = v.w;
    __syncthreads();

    uint2 o;
    o.x = h2_as_u32(__floats2half2_rn(s[c4 + 0][r], s[c4 + 1][r]));
    o.y = h2_as_u32(__floats2half2_rn(s[c4 + 2][r], s[c4 + 3][r]));
    *(uint2*)(dst + ((size_t)e * N + 32 * bn + r) * K + 32 * bk + c4) = o;
}

// ---------------------------------------------------------------------------
// Grouped GEMM: C = op(A @ W^T[e] + bias[e])
// 128x128 block tile, BK=64, 8 warps (2x4), 64x32 warp tile, fp16 m16n8k16,
// fp32 accumulate, cp.async double-buffer.
//   LAYER1: A = g_a1 gathered via g_perm (zero-fill pads), relu, -> g_h sorted
//  !LAYER1: A = g_h contiguous, -> scatter fp32 to out via g_perm
// ---------------------------------------------------------------------------
template <int K, int NTOT, bool LAYER1>
__global__ __launch_bounds__(256, 2)
void gemm_kernel(const float* __restrict__ bias, float* __restrict__ Oout) {
    extern __shared__ __half smem[];
    __half* AsBase = smem;                    // 2 stages TM x BK (stride ST)
    __half* BsBase = smem + 2 * AS_SZ;        // 2 stages BN x BK (stride ST)

    const int tile = blockIdx.x;
    const int e = g_tile_expert[tile];
    if (e < 0) return;

    const __half* Wt = LAYER1 ? g_w1t : g_w2t;

    const int n0 = blockIdx.y * BN;
    const __half* Brow0 = Wt + ((size_t)e * NTOT + n0) * K;
    const float*  bp    = bias + (size_t)e * NTOT + n0;

    const int tid  = threadIdx.x;
    const int lane = tid & 31;
    const int warp = tid >> 5;
    const int wm   = warp >> 2;  // 0..1
    const int wn   = warp & 3;   // 0..3

    // A row sources. LAYER1: gather via perm (4 rows per thread, pads -> null).
    const __half* arow[4];
#pragma unroll
    for (int j = 0; j < 4; j++) {
        int r = (tid >> 3) + 32 * j;
        if (LAYER1) {
            int tok = g_perm[tile * TM + r];
            arow[j] = (tok >= 0) ? (g_a1 + (size_t)tok * K) : nullptr;
        } else {
            arow[j] = g_h + ((size_t)tile * TM + r) * K;
        }
    }

    float acc[4][4][4];
#pragma unroll
    for (int i = 0; i < 4; i++)
#pragma unroll
        for (int j = 0; j < 4; j++)
#pragma unroll
            for (int q = 0; q < 4; q++) acc[i][j][q] = 0.f;

    const int aco = (tid & 7) * 8;   // A: 16B chunk col offset within BK

    // Stage 128 rows x 64 halves for A (per-row pointers) and B (contiguous).
    auto stage = [&](int k0, int buf) {
        __half* as = AsBase + buf * AS_SZ;
        __half* bs = BsBase + buf * BS_SZ;
#pragma unroll
        for (int j = 0; j < 4; j++) {
            int r = (tid >> 3) + 32 * j;
            const __half* src = arow[j] ? (arow[j] + k0 + aco) : g_a1;
            cp_async16_z(&as[r * ST + aco], src, arow[j] != nullptr);
        }
#pragma unroll
        for (int j = 0; j < 4; j++) {
            int c = tid + 256 * j;
            int r = c >> 3;
            int co = (c & 7) * 8;
            cp_async16(&bs[r * ST + co], Brow0 + (size_t)r * K + k0 + co);
        }
    };

    constexpr int NIT = K / BK;

    stage(0, 0);
    asm volatile("cp.async.commit_group;\n");

    for (int it = 0; it < NIT; it++) {
        const int buf = it & 1;
        if (it + 1 < NIT) {
            stage((it + 1) * BK, buf ^ 1);
            asm volatile("cp.async.commit_group;\n");
            asm volatile("cp.async.wait_group 1;\n");
        } else {
            asm volatile("cp.async.wait_group 0;\n");
        }
        __syncthreads();

        const __half* As = AsBase + buf * AS_SZ;
        const __half* Bs = BsBase + buf * BS_SZ;

#pragma unroll
        for (int ks = 0; ks < BK / 16; ks++) {
            const int kq = ks * 16 + (lane & 3) * 2;
            uint32_t af[4][4], bf[4][2];
#pragma unroll
            for (int mf = 0; mf < 4; mf++) {
                int m = wm * 64 + mf * 16 + (lane >> 2);
                // m16n8k16 f16 A frag: a0=(m,k:k+1) a1=(m+8,k:k+1) a2=(m,k+8:k+9) a3=(m+8,k+8:k+9)
                af[mf][0] = *(const uint32_t*)&As[m * ST + kq];
                af[mf][1] = *(const uint32_t*)&As[(m + 8) * ST + kq];
                af[mf][2] = *(const uint32_t*)&As[m * ST + kq + 8];
                af[mf][3] = *(const uint32_t*)&As[(m + 8) * ST + kq + 8];
            }
#pragma unroll
            for (int nf = 0; nf < 4; nf++) {
                int n = wn * 32 + nf * 8 + (lane >> 2);
                // B frag (col): b0=(k:k+1, n), b1=(k+8:k+9, n); Bs rows n-major, k contiguous
                bf[nf][0] = *(const uint32_t*)&Bs[n * ST + kq];
                bf[nf][1] = *(const uint32_t*)&Bs[n * ST + kq + 8];
            }
#pragma unroll
            for (int mf = 0; mf < 4; mf++)
#pragma unroll
                for (int nf = 0; nf < 4; nf++) {
                    asm volatile(
                        "mma.sync.aligned.m16n8k16.row.col.f32.f16.f16.f32 "
                        "{%0,%1,%2,%3}, {%4,%5,%6,%7}, {%8,%9}, {%0,%1,%2,%3};\n"
                        : "+f"(acc[mf][nf][0]), "+f"(acc[mf][nf][1]),
                          "+f"(acc[mf][nf][2]), "+f"(acc[mf][nf][3])
                        : "r"(af[mf][0]), "r"(af[mf][1]),
                          "r"(af[mf][2]), "r"(af[mf][3]),
                          "r"(bf[nf][0]), "r"(bf[nf][1]));
                }
        }
        __syncthreads();
    }

    // Epilogue: bias (+relu); layer1 -> half g_h (sorted), layer2 -> scatter fp32.
#pragma unroll
    for (int mf = 0; mf < 4; mf++) {
#pragma unroll
        for (int half_i = 0; half_i < 2; half_i++) {
            int r = wm * 64 + mf * 16 + (lane >> 2) + half_i * 8;
            float* orow_f = nullptr;
            __half* orow_h = nullptr;
            if (!LAYER1) {
                int tok = g_perm[tile * TM + r];
                if (tok >= 0) orow_f = Oout + (size_t)tok * NTOT + n0;
            } else {
                orow_h = g_h + ((size_t)tile * TM + r) * NTOT + n0;
            }
#pragma unroll
            for (int nf = 0; nf < 4; nf++) {
                int c = wn * 32 + nf * 8 + 2 * (lane & 3);
                float v0 = acc[mf][nf][half_i * 2 + 0] + bp[c];
                float v1 = acc[mf][nf][half_i * 2 + 1] + bp[c + 1];
                if (LAYER1) { v0 = fmaxf(v0, 0.f); v1 = fmaxf(v1, 0.f); }
                if (!LAYER1) {
                    if (orow_f) { orow_f[c] = v0; orow_f[c + 1] = v1; }
                } else {
                    *(uint32_t*)&orow_h[c] = h2_as_u32(__floats2half2_rn(v0, v1));
                }
            }
        }
    }
}

extern "C" void kernel_launch(void* const* d_in, const int* in_sizes, int n_in,
                              void* d_out, int out_size) {
    const float* x      = (const float*)d_in[0];
    const int*   groups = (const int*)d_in[1];
    const float* W1     = (const float*)d_in[2];
    const float* b1     = (const float*)d_in[3];
    const float* W2     = (const float*)d_in[4];
    const float* b2     = (const float*)d_in[5];
    float*       out    = (float*)d_out;

    // One-time side streams + events for capture-legal fork/join.
    static cudaStream_t s2 = nullptr, s3 = nullptr;
    static cudaEvent_t evFork = nullptr, evW1 = nullptr, evW2 = nullptr, evX = nullptr;
    if (!s2) {
        cudaStreamCreateWithFlags(&s2, cudaStreamNonBlocking);
        cudaStreamCreateWithFlags(&s3, cudaStreamNonBlocking);
        cudaEventCreateWithFlags(&evFork, cudaEventDisableTiming);
        cudaEventCreateWithFlags(&evW1,   cudaEventDisableTiming);
        cudaEventCreateWithFlags(&evW2,   cudaEventDisableTiming);
        cudaEventCreateWithFlags(&evX,    cudaEventDisableTiming);
    }

    cudaFuncSetAttribute(gemm_kernel<D_IN, D_H, true>,
                         cudaFuncAttributeMaxDynamicSharedMemorySize, SMEM_BYTES);
    cudaFuncSetAttribute(gemm_kernel<D_H, D_OUT, false>,
                         cudaFuncAttributeMaxDynamicSharedMemorySize, SMEM_BYTES);

    // Fork: W transposes on s2 (W1 first — needed earliest), x convert on s3.
    cudaEventRecord(evFork, 0);
    cudaStreamWaitEvent(s2, evFork, 0);
    cudaStreamWaitEvent(s3, evFork, 0);
    prep_w_kernel<D_IN, D_H, false><<<dim3(D_H / 32, D_IN / 32, NE), 256, 0, s2>>>(W1);
    cudaEventRecord(evW1, s2);
    prep_w_kernel<D_H, D_OUT, true><<<dim3(D_OUT / 32, D_H / 32, NE), 256, 0, s2>>>(W2);
    cudaEventRecord(evW2, s2);
    convert_x_kernel<<<(B_TOK * D_IN) / (256 * 8), 256, 0, s3>>>(x);
    cudaEventRecord(evX, s3);

    // Main stream: routing only.
    route_kernel<<<1, 1024>>>(groups);

    // Join: GEMM1 needs W1^T + x_half (+ route via program order).
    cudaStreamWaitEvent(0, evW1, 0);
    cudaStreamWaitEvent(0, evX, 0);
    gemm_kernel<D_IN, D_H, true>
        <<<dim3(NT_MAX, D_H / BN), 256, SMEM_BYTES>>>(b1, nullptr);

    // GEMM2 needs W2^T (long done by now).
    cudaStreamWaitEvent(0, evW2, 0);
    gemm_kernel<D_H, D_OUT, false>
        <<<dim3(NT_MAX, D_OUT / BN), 256, SMEM_BYTES>>>(b2, out);
}

// round 14
// speedup vs baseline: 1.1675x; 1.0384x over previous
#include <cuda_runtime.h>
#include <cuda_fp16.h>
#include <cstdint>
#include <cstddef>

// SubnetGate hard-routed MoE MLP, sm_103 harness (no tcgen05 under compute_103).
//   out[t] = relu(x[t] @ W1[e] + b1[e]) @ W2[e] + b2[e],  e = groups[t]
// B=8192, D_IN=512, D_H=2048, D_OUT=512, E=8, fp32 I/O (groups int32, probed).
//
// R14: scheduling-only change vs R13. prep_w2 (48MB of DRAM traffic, needed
// only by GEMM2) is deferred out of the pre-GEMM1 window (it now waits on the
// route event and overlaps GEMM1, which has ~7TB/s of DRAM headroom).
// Pre-GEMM window traffic: 121MB -> 73MB.

namespace {
constexpr int B_TOK  = 8192;
constexpr int D_IN   = 512;
constexpr int D_H    = 2048;
constexpr int D_OUT  = 512;
constexpr int NE     = 8;
constexpr int TM     = 128;
constexpr int NT_MAX = 72;            // sum ceil(c_e/128) <= 64+7
constexpr int ROWS   = NT_MAX * TM;   // 9216
constexpr int BK     = 64;            // halves per k-tile (128B rows)
constexpr int BN     = 128;
constexpr int ST     = 72;            // smem row stride in halves (conflict-free frag loads)
constexpr int AS_SZ  = TM * ST;       // halves per stage
constexpr int BS_SZ  = BN * ST;
constexpr int SMEM_BYTES = 2 * (AS_SZ + BS_SZ) * 2;   // 73728 B
}

__device__ int g_perm[ROWS];            // sorted pos -> token (-1 = pad)
__device__ int g_tile_expert[NT_MAX];   // tile -> expert (-1 inactive)
__device__ __align__(16) __half g_a1[(size_t)B_TOK * D_IN];       // x as half, TOKEN order
__device__ __align__(16) __half g_w1t[(size_t)NE * D_H * D_IN];   // W1^T [e][n][k] half
__device__ __align__(16) __half g_w2t[(size_t)NE * D_OUT * D_H];  // W2^T [e][n][k] half
__device__ __align__(16) __half g_h[(size_t)ROWS * D_H];          // hidden (half, sorted)

__device__ __forceinline__ uint32_t h2_as_u32(__half2 h) {
    return *reinterpret_cast<uint32_t*>(&h);
}

__device__ __forceinline__ void cp_async16(void* smem_dst, const void* gsrc) {
    uint32_t s = (uint32_t)__cvta_generic_to_shared(smem_dst);
    asm volatile("cp.async.cg.shared.global [%0], [%1], 16;\n" :: "r"(s), "l"(gsrc));
}
// Predicated variant: pred=false => src-size 0 => zero-fill 16B.
__device__ __forceinline__ void cp_async16_z(void* smem_dst, const void* gsrc, bool pred) {
    uint32_t s = (uint32_t)__cvta_generic_to_shared(smem_dst);
    int sz = pred ? 16 : 0;
    asm volatile("cp.async.cg.shared.global [%0], [%1], 16, %2;\n"
                 :: "r"(s), "l"(gsrc), "r"(sz));
}

// ---------------------------------------------------------------------------
// Router (R10-proven): single block, shared-counter counting sort into
// 128-row padded per-expert tiles. Probes int32 vs int64 groups layout.
// ---------------------------------------------------------------------------
__global__ void route_kernel(const int* __restrict__ g32) {
    __shared__ int cnt[NE];
    __shared__ int base[NE + 1];
    __shared__ int cur[NE];
    __shared__ int odd_or;
    const int tid = threadIdx.x;

    if (tid < NE) cnt[tid] = 0;
    if (tid == 0) odd_or = 0;
    __syncthreads();

    // dtype probe: int64 data (values 0..7, LE) => all odd int32 words zero
    int acc_or = 0;
    for (int i = 2 * tid + 1; i < B_TOK; i += 2 * blockDim.x) acc_or |= g32[i];
    if (acc_or) atomicOr(&odd_or, 1);
    __syncthreads();
    const bool is_i32 = (odd_or != 0);

    for (int t = tid; t < B_TOK; t += blockDim.x) {
        int e = (is_i32 ? g32[t] : g32[2 * t]) & (NE - 1);
        atomicAdd(&cnt[e], 1);
    }
    __syncthreads();

    if (tid == 0) {
        int b = 0;
        for (int e = 0; e < NE; e++) {
            base[e] = b; cur[e] = b;
            b += ((cnt[e] + TM - 1) / TM) * TM;
        }
        base[NE] = b;
    }
    __syncthreads();

    for (int i = tid; i < ROWS; i += blockDim.x) g_perm[i] = -1;
    for (int t = tid; t < NT_MAX; t += blockDim.x) {
        int row0 = t * TM;
        int e = -1;
        if (row0 < base[NE])
            for (int k = 0; k < NE; k++)
                if (row0 >= base[k] && row0 < base[k + 1]) e = k;
        g_tile_expert[t] = e;
    }
    __syncthreads();

    for (int t = tid; t < B_TOK; t += blockDim.x) {
        int e = (is_i32 ? g32[t] : g32[2 * t]) & (NE - 1);
        int pos = atomicAdd(&cur[e], 1);
        g_perm[pos] = t;
    }
}

// ---------------------------------------------------------------------------
// Convert x -> half in TOKEN order (no routing dependency; coalesced).
// Each thread: 8 floats -> 16B half store. grid 2048 x 256.
// ---------------------------------------------------------------------------
__global__ void convert_x_kernel(const float* __restrict__ x) {
    const size_t base = ((size_t)blockIdx.x * 256 + threadIdx.x) * 8;
    float4 a = *(const float4*)(x + base);
    float4 b = *(const float4*)(x + base + 4);
    uint4 o;
    o.x = h2_as_u32(__floats2half2_rn(a.x, a.y));
    o.y = h2_as_u32(__floats2half2_rn(a.z, a.w));
    o.z = h2_as_u32(__floats2half2_rn(b.x, b.y));
    o.w = h2_as_u32(__floats2half2_rn(b.z, b.w));
    *(uint4*)(g_a1 + base) = o;
}

// ---------------------------------------------------------------------------
// Prep (R10-proven): transpose W [e][K][N] -> W^T [e][N][K], converted to half.
// 32x32 fp32 smem tiles; grid (N/32, K/32, E), 256 threads.
// ---------------------------------------------------------------------------
template <int K, int N, bool W2SEL>
__global__ void prep_w_kernel(const float* __restrict__ src) {
    __shared__ float s[32][33];
    __half* dst = W2SEL ? g_w2t : g_w1t;
    const int tid = threadIdx.x;
    const int bn = blockIdx.x, bk = blockIdx.y, e = blockIdx.z;
    const int r  = tid >> 3;
    const int c4 = (tid & 7) * 4;

    float4 v = *(const float4*)(src + ((size_t)e * K + 32 * bk + r) * N + 32 * bn + c4);
    s[r][c4 + 0] = v.x; s[r][c4 + 1] = v.y; s[r][c4 + 2] = v.z; s[r][c4 + 3] = v.w;
    __syncthreads();

    uint2 o;
    o.x = h2_as_u32(__floats2half2_rn(s[c4 + 0][r], s[c4 + 1][r]));
    o.y = h2_as_u32(__floats2half2_rn(s[c4 + 2][r], s[c4 + 3][r]));
    *(uint2*)(dst + ((size_t)e * N + 32 * bn + r) * K + 32 * bk + c4) = o;
}

// ---------------------------------------------------------------------------
// Grouped GEMM: C = op(A @ W^T[e] + bias[e])
// 128x128 block tile, BK=64, 8 warps (2x4), 64x32 warp tile, fp16 m16n8k16,
// fp32 accumulate, cp.async double-buffer.
//   LAYER1: A = g_a1 gathered via g_perm (zero-fill pads), relu, -> g_h sorted
//  !LAYER1: A = g_h contiguous, -> scatter fp32 to out via g_perm
// ---------------------------------------------------------------------------
template <int K, int NTOT, bool LAYER1>
__global__ __launch_bounds__(256, 2)
void gemm_kernel(const float* __restrict__ bias, float* __restrict__ Oout) {
    extern __shared__ __half smem[];
    __half* AsBase = smem;                    // 2 stages TM x BK (stride ST)
    __half* BsBase = smem + 2 * AS_SZ;        // 2 stages BN x BK (stride ST)

    const int tile = blockIdx.x;
    const int e = g_tile_expert[tile];
    if (e < 0) return;

    const __half* Wt = LAYER1 ? g_w1t : g_w2t;

    const int n0 = blockIdx.y * BN;
    const __half* Brow0 = Wt + ((size_t)e * NTOT + n0) * K;
    const float*  bp    = bias + (size_t)e * NTOT + n0;

    const int tid  = threadIdx.x;
    const int lane = tid & 31;
    const int warp = tid >> 5;
    const int wm   = warp >> 2;  // 0..1
    const int wn   = warp & 3;   // 0..3

    // A row sources. LAYER1: gather via perm (4 rows per thread, pads -> null).
    const __half* arow[4];
#pragma unroll
    for (int j = 0; j < 4; j++) {
        int r = (tid >> 3) + 32 * j;
        if (LAYER1) {
            int tok = g_perm[tile * TM + r];
            arow[j] = (tok >= 0) ? (g_a1 + (size_t)tok * K) : nullptr;
        } else {
            arow[j] = g_h + ((size_t)tile * TM + r) * K;
        }
    }

    float acc[4][4][4];
#pragma unroll
    for (int i = 0; i < 4; i++)
#pragma unroll
        for (int j = 0; j < 4; j++)
#pragma unroll
            for (int q = 0; q < 4; q++) acc[i][j][q] = 0.f;

    const int aco = (tid & 7) * 8;   // A: 16B chunk col offset within BK

    // Stage 128 rows x 64 halves for A (per-row pointers) and B (contiguous).
    auto stage = [&](int k0, int buf) {
        __half* as = AsBase + buf * AS_SZ;
        __half* bs = BsBase + buf * BS_SZ;
#pragma unroll
        for (int j = 0; j < 4; j++) {
            int r = (tid >> 3) + 32 * j;
            const __half* src = arow[j] ? (arow[j] + k0 + aco) : g_a1;
            cp_async16_z(&as[r * ST + aco], src, arow[j] != nullptr);
        }
#pragma unroll
        for (int j = 0; j < 4; j++) {
            int c = tid + 256 * j;
            int r = c >> 3;
            int co = (c & 7) * 8;
            cp_async16(&bs[r * ST + co], Brow0 + (size_t)r * K + k0 + co);
        }
    };

    constexpr int NIT = K / BK;

    stage(0, 0);
    asm volatile("cp.async.commit_group;\n");

    for (int it = 0; it < NIT; it++) {
        const int buf = it & 1;
        if (it + 1 < NIT) {
            stage((it + 1) * BK, buf ^ 1);
            asm volatile("cp.async.commit_group;\n");
            asm volatile("cp.async.wait_group 1;\n");
        } else {
            asm volatile("cp.async.wait_group 0;\n");
        }
        __syncthreads();

        const __half* As = AsBase + buf * AS_SZ;
        const __half* Bs = BsBase + buf * BS_SZ;

#pragma unroll
        for (int ks = 0; ks < BK / 16; ks++) {
            const int kq = ks * 16 + (lane & 3) * 2;
            uint32_t af[4][4], bf[4][2];
#pragma unroll
            for (int mf = 0; mf < 4; mf++) {
                int m = wm * 64 + mf * 16 + (lane >> 2);
                // m16n8k16 f16 A frag: a0=(m,k:k+1) a1=(m+8,k:k+1) a2=(m,k+8:k+9) a3=(m+8,k+8:k+9)
                af[mf][0] = *(const uint32_t*)&As[m * ST + kq];
                af[mf][1] = *(const uint32_t*)&As[(m + 8) * ST + kq];
                af[mf][2] = *(const uint32_t*)&As[m * ST + kq + 8];
                af[mf][3] = *(const uint32_t*)&As[(m + 8) * ST + kq + 8];
            }
#pragma unroll
            for (int nf = 0; nf < 4; nf++) {
                int n = wn * 32 + nf * 8 + (lane >> 2);
                // B frag (col): b0=(k:k+1, n), b1=(k+8:k+9, n); Bs rows n-major, k contiguous
                bf[nf][0] = *(const uint32_t*)&Bs[n * ST + kq];
                bf[nf][1] = *(const uint32_t*)&Bs[n * ST + kq + 8];
            }
#pragma unroll
            for (int mf = 0; mf < 4; mf++)
#pragma unroll
                for (int nf = 0; nf < 4; nf++) {
                    asm volatile(
                        "mma.sync.aligned.m16n8k16.row.col.f32.f16.f16.f32 "
                        "{%0,%1,%2,%3}, {%4,%5,%6,%7}, {%8,%9}, {%0,%1,%2,%3};\n"
                        : "+f"(acc[mf][nf][0]), "+f"(acc[mf][nf][1]),
                          "+f"(acc[mf][nf][2]), "+f"(acc[mf][nf][3])
                        : "r"(af[mf][0]), "r"(af[mf][1]),
                          "r"(af[mf][2]), "r"(af[mf][3]),
                          "r"(bf[nf][0]), "r"(bf[nf][1]));
                }
        }
        __syncthreads();
    }

    // Epilogue: bias (+relu); layer1 -> half g_h (sorted), layer2 -> scatter fp32.
#pragma unroll
    for (int mf = 0; mf < 4; mf++) {
#pragma unroll
        for (int half_i = 0; half_i < 2; half_i++) {
            int r = wm * 64 + mf * 16 + (lane >> 2) + half_i * 8;
            float* orow_f = nullptr;
            __half* orow_h = nullptr;
            if (!LAYER1) {
                int tok = g_perm[tile * TM + r];
                if (tok >= 0) orow_f = Oout + (size_t)tok * NTOT + n0;
            } else {
                orow_h = g_h + ((size_t)tile * TM + r) * NTOT + n0;
            }
#pragma unroll
            for (int nf = 0; nf < 4; nf++) {
                int c = wn * 32 + nf * 8 + 2 * (lane & 3);
                float v0 = acc[mf][nf][half_i * 2 + 0] + bp[c];
                float v1 = acc[mf][nf][half_i * 2 + 1] + bp[c + 1];
                if (LAYER1) { v0 = fmaxf(v0, 0.f); v1 = fmaxf(v1, 0.f); }
                if (!LAYER1) {
                    if (orow_f) { orow_f[c] = v0; orow_f[c + 1] = v1; }
                } else {
                    *(uint32_t*)&orow_h[c] = h2_as_u32(__floats2half2_rn(v0, v1));
                }
            }
        }
    }
}

extern "C" void kernel_launch(void* const* d_in, const int* in_sizes, int n_in,
                              void* d_out, int out_size) {
    const float* x      = (const float*)d_in[0];
    const int*   groups = (const int*)d_in[1];
    const float* W1     = (const float*)d_in[2];
    const float* b1     = (const float*)d_in[3];
    const float* W2     = (const float*)d_in[4];
    const float* b2     = (const float*)d_in[5];
    float*       out    = (float*)d_out;

    // One-time side streams + events for capture-legal fork/join.
    static cudaStream_t s2 = nullptr, s3 = nullptr;
    static cudaEvent_t evFork = nullptr, evW1 = nullptr, evW2 = nullptr,
                       evX = nullptr, evRoute = nullptr;
    if (!s2) {
        cudaStreamCreateWithFlags(&s2, cudaStreamNonBlocking);
        cudaStreamCreateWithFlags(&s3, cudaStreamNonBlocking);
        cudaEventCreateWithFlags(&evFork,  cudaEventDisableTiming);
        cudaEventCreateWithFlags(&evW1,    cudaEventDisableTiming);
        cudaEventCreateWithFlags(&evW2,    cudaEventDisableTiming);
        cudaEventCreateWithFlags(&evX,     cudaEventDisableTiming);
        cudaEventCreateWithFlags(&evRoute, cudaEventDisableTiming);
    }

    cudaFuncSetAttribute(gemm_kernel<D_IN, D_H, true>,
                         cudaFuncAttributeMaxDynamicSharedMemorySize, SMEM_BYTES);
    cudaFuncSetAttribute(gemm_kernel<D_H, D_OUT, false>,
                         cudaFuncAttributeMaxDynamicSharedMemorySize, SMEM_BYTES);

    // Fork: W1^T on s2, x convert on s3. prep_w2 is NOT in this window.
    cudaEventRecord(evFork, 0);
    cudaStreamWaitEvent(s2, evFork, 0);
    cudaStreamWaitEvent(s3, evFork, 0);
    prep_w_kernel<D_IN, D_H, false><<<dim3(D_H / 32, D_IN / 32, NE), 256, 0, s2>>>(W1);
    cudaEventRecord(evW1, s2);
    convert_x_kernel<<<(B_TOK * D_IN) / (256 * 8), 256, 0, s3>>>(x);
    cudaEventRecord(evX, s3);

    // Main stream: routing.
    route_kernel<<<1, 1024>>>(groups);
    cudaEventRecord(evRoute, 0);

    // Deferred: W2^T starts only after route completes (i.e. overlapping
    // GEMM1, which has ample DRAM headroom), keeping the pre-GEMM1 window
    // free for prep_w1 + convert_x.
    cudaStreamWaitEvent(s2, evRoute, 0);
    prep_w_kernel<D_H, D_OUT, true><<<dim3(D_OUT / 32, D_H / 32, NE), 256, 0, s2>>>(W2);
    cudaEventRecord(evW2, s2);

    // Join: GEMM1 needs W1^T + x_half (+ route via program order).
    cudaStreamWaitEvent(0, evW1, 0);
    cudaStreamWaitEvent(0, evX, 0);
    gemm_kernel<D_IN, D_H, true>
        <<<dim3(NT_MAX, D_H / BN), 256, SMEM_BYTES>>>(b1, nullptr);

    // GEMM2 needs W2^T (done well before GEMM1 finishes).
    cudaStreamWaitEvent(0, evW2, 0);
    gemm_kernel<D_H, D_OUT, false>
        <<<dim3(NT_MAX, D_OUT / BN), 256, SMEM_BYTES>>>(b2, out);
}